// round 5
// baseline (speedup 1.0000x reference)
#include <cuda_runtime.h>
#include <stdint.h>

// Problem constants (fixed by the reference: B=4, S=4096, D=2, 3 RK2 steps)
#define BB    4
#define SS    4096
#define WPR   (SS / 32)            // 128 bitmask words per row
#define NWRDS (BB * SS * WPR)      // 2,097,152 words (8 MB)
#define NROWS (BB * SS)            // 16384 rows
#define CAP   96                   // padded index capacity per row (mean 41, sd 6.4)
#define DT_F      0.1f
#define HALF_DT_F 0.05f
#define EPS_F     1e-8f

// Force-kernel tiling: 8 threads per row, 32 rows per block.
#define T_PER_ROW 8
#define ROWS_PB   32
#define IPT       (CAP / T_PER_ROW)   // 12 indices per thread
#define WPT       (WPR / T_PER_ROW)   // 16 bitmask words per thread (fallback path)

// ---- scratch (static device globals; no runtime allocation) ----
__device__ __align__(16) uint32_t       g_bits[NWRDS];        // 8 MB bitmask
__device__ __align__(16) unsigned short g_idx[NROWS * CAP];   // 3 MB padded CSR indices
__device__               int            g_cnt[NROWS];         // true nnz per row
__device__ __align__(16) float2         g_p[NROWS];
__device__ __align__(16) float2         g_star[NROWS];
__device__ __align__(16) float2         g_k1[NROWS];
__device__               float          g_r[NROWS];

// ============================================================================
// 1) Compress dense fp32 0/1 mask -> bitmask via warp ballots (HBM-bound).
// ============================================================================
__global__ void compress_kernel(const float* __restrict__ mask) {
    const int lane   = threadIdx.x & 31;
    const int warp   = (blockIdx.x * blockDim.x + threadIdx.x) >> 5;
    const int nwarps = (gridDim.x * blockDim.x) >> 5;

    for (size_t w = (size_t)warp * 8; w < (size_t)NWRDS; w += (size_t)nwarps * 8) {
        float v0 = mask[(w + 0) * 32 + lane];
        float v1 = mask[(w + 1) * 32 + lane];
        float v2 = mask[(w + 2) * 32 + lane];
        float v3 = mask[(w + 3) * 32 + lane];
        float v4 = mask[(w + 4) * 32 + lane];
        float v5 = mask[(w + 5) * 32 + lane];
        float v6 = mask[(w + 6) * 32 + lane];
        float v7 = mask[(w + 7) * 32 + lane];

        unsigned b0 = __ballot_sync(0xFFFFFFFFu, v0 != 0.0f);
        unsigned b1 = __ballot_sync(0xFFFFFFFFu, v1 != 0.0f);
        unsigned b2 = __ballot_sync(0xFFFFFFFFu, v2 != 0.0f);
        unsigned b3 = __ballot_sync(0xFFFFFFFFu, v3 != 0.0f);
        unsigned b4 = __ballot_sync(0xFFFFFFFFu, v4 != 0.0f);
        unsigned b5 = __ballot_sync(0xFFFFFFFFu, v5 != 0.0f);
        unsigned b6 = __ballot_sync(0xFFFFFFFFu, v6 != 0.0f);
        unsigned b7 = __ballot_sync(0xFFFFFFFFu, v7 != 0.0f);

        if (lane == 0) {
            uint4* dst = reinterpret_cast<uint4*>(g_bits + w);  // w % 8 == 0 -> 32B aligned
            dst[0] = make_uint4(b0, b1, b2, b3);
            dst[1] = make_uint4(b4, b5, b6, b7);
        }
    }
}

// ============================================================================
// 2) Build padded CSR index lists from the bitmask. One warp per row:
//    popc + warp prefix scan + in-bit-order scatter -> fully deterministic.
// ============================================================================
__global__ void build_idx_kernel() {
    const int warp_in_blk = threadIdx.x >> 5;
    const int lane        = threadIdx.x & 31;
    const int row         = blockIdx.x * (blockDim.x >> 5) + warp_in_blk;
    if (row >= NROWS) return;

    // Each lane owns 4 consecutive words of the row.
    const uint4 w4 = reinterpret_cast<const uint4*>(g_bits + (size_t)row * WPR)[lane];
    const int n = __popc(w4.x) + __popc(w4.y) + __popc(w4.z) + __popc(w4.w);

    // Exclusive warp prefix scan of n.
    int pfx = n;
#pragma unroll
    for (int off = 1; off < 32; off <<= 1) {
        int v = __shfl_up_sync(0xFFFFFFFFu, pfx, off);
        if (lane >= off) pfx += v;
    }
    const int total = __shfl_sync(0xFFFFFFFFu, pfx, 31);
    pfx -= n;  // exclusive

    if (lane == 31) g_cnt[row] = total;

    // Scatter column indices in bit order.
    unsigned short* dst = g_idx + (size_t)row * CAP;
    int slot = pfx;
    const int colbase = lane * 128;  // lane*4 words * 32 bits
    uint32_t ws[4] = {w4.x, w4.y, w4.z, w4.w};
#pragma unroll
    for (int k = 0; k < 4; k++) {
        uint32_t w = ws[k];
        while (w) {
            int c = __ffs(w) - 1;
            w &= (w - 1);
            if (slot < CAP) dst[slot] = (unsigned short)(colbase + k * 32 + c);
            slot++;
        }
    }
}

// ============================================================================
// Force helpers
// ============================================================================
// Fallback: sparse scan of the bitmask row (only if cnt > CAP; ~never).
__device__ __forceinline__ void accum_word(uint32_t w, int base,
                                           const float2* __restrict__ sp,
                                           float& ax, float& ay) {
    while (w) {
        int c = __ffs(w) - 1;
        w &= (w - 1);
        float2 v = sp[base + c];
        ax += v.x;
        ay += v.y;
    }
}

__device__ __forceinline__ void row_force(const float2* __restrict__ sp,
                                          int row, int t,
                                          float& ax, float& ay) {
    ax = 0.0f; ay = 0.0f;
    const int cnt = g_cnt[row];

    if (cnt <= CAP) {
        // Branch-free padded-CSR gather: 12 independent LDS float2 per thread.
        const unsigned short* ip = g_idx + (size_t)row * CAP + t * IPT;
        const uint2* p2 = reinterpret_cast<const uint2*>(ip);  // 24B offset -> 8B aligned
        uint2 a0 = p2[0], a1 = p2[1], a2 = p2[2];
        unsigned short id[IPT];
        id[0]  = (unsigned short)(a0.x);        id[1]  = (unsigned short)(a0.x >> 16);
        id[2]  = (unsigned short)(a0.y);        id[3]  = (unsigned short)(a0.y >> 16);
        id[4]  = (unsigned short)(a1.x);        id[5]  = (unsigned short)(a1.x >> 16);
        id[6]  = (unsigned short)(a1.y);        id[7]  = (unsigned short)(a1.y >> 16);
        id[8]  = (unsigned short)(a2.x);        id[9]  = (unsigned short)(a2.x >> 16);
        id[10] = (unsigned short)(a2.y);        id[11] = (unsigned short)(a2.y >> 16);

        const int off = t * IPT;
#pragma unroll
        for (int j = 0; j < IPT; j++) {
            int sel = (off + j < cnt) ? (int)id[j] : SS;  // SS -> zero pad slot
            float2 v = sp[sel];
            ax += v.x;
            ay += v.y;
        }
    } else {
        // Correctness fallback: full bitmask scan (independent of g_idx).
        const uint4* wr = reinterpret_cast<const uint4*>(
                              g_bits + (size_t)row * WPR) + t * (WPT / 4);
#pragma unroll
        for (int q = 0; q < WPT / 4; q++) {
            uint4 w4   = wr[q];
            int   base = (t * WPT + q * 4) * 32;
            accum_word(w4.x, base,      sp, ax, ay);
            accum_word(w4.y, base + 32, sp, ax, ay);
            accum_word(w4.z, base + 64, sp, ax, ay);
            accum_word(w4.w, base + 96, sp, ax, ay);
        }
    }

#pragma unroll
    for (int offp = T_PER_ROW / 2; offp > 0; offp >>= 1) {
        ax += __shfl_down_sync(0xFFFFFFFFu, ax, offp, T_PER_ROW);
        ay += __shfl_down_sync(0xFFFFFFFFu, ay, offp, T_PER_ROW);
    }
}

// ============================================================================
// 3a) stepA: from p -> (r, k1, psi_star).   p_in==nullptr means "use g_p".
// ============================================================================
__global__ void __launch_bounds__(ROWS_PB * T_PER_ROW)
stepA_kernel(const float2* __restrict__ p_in) {
    __shared__ float2 sp[SS + 1];  // full per-batch state + zero pad slot
    const int b = blockIdx.y;
    const float2* src2 = p_in ? (p_in + b * SS) : (g_p + b * SS);

    {
        const float4* src = reinterpret_cast<const float4*>(src2);
        float4*       dst = reinterpret_cast<float4*>(sp);
        for (int i = threadIdx.x; i < SS / 2; i += blockDim.x) dst[i] = src[i];
        if (threadIdx.x == 0) sp[SS] = make_float2(0.0f, 0.0f);
    }
    __syncthreads();

    const int lrow = threadIdx.x / T_PER_ROW;
    const int row  = b * SS + blockIdx.x * ROWS_PB + lrow;
    const int t    = threadIdx.x % T_PER_ROW;

    float ax, ay;
    row_force(sp, row, t, ax, ay);

    if (t == 0) {
        float2 pi = sp[blockIdx.x * ROWS_PB + lrow];
        float  r  = sqrtf(pi.x * pi.x + pi.y * pi.y);
        float k1x = ax - pi.x;
        float k1y = ay - pi.y;
        float sx  = fmaf(DT_F, k1x, pi.x);
        float sy  = fmaf(DT_F, k1y, pi.y);
        float sn  = sqrtf(sx * sx + sy * sy);
        float sc  = r / (sn + EPS_F);
        g_star[row] = make_float2(sx * sc, sy * sc);
        g_k1[row]   = make_float2(k1x, k1y);
        g_r[row]    = r;
    }
}

// ============================================================================
// 3b) stepB: from (psi_star, k1, p, r) -> p_new.
//     p_old==nullptr -> use g_p.  p_out==nullptr -> write g_p.
// ============================================================================
__global__ void __launch_bounds__(ROWS_PB * T_PER_ROW)
stepB_kernel(const float2* __restrict__ p_old, float2* __restrict__ p_out) {
    __shared__ float2 sp[SS + 1];  // psi_star for this batch + zero pad slot
    const int b = blockIdx.y;

    {
        const float4* src = reinterpret_cast<const float4*>(g_star + b * SS);
        float4*       dst = reinterpret_cast<float4*>(sp);
        for (int i = threadIdx.x; i < SS / 2; i += blockDim.x) dst[i] = src[i];
        if (threadIdx.x == 0) sp[SS] = make_float2(0.0f, 0.0f);
    }
    __syncthreads();

    const int lrow = threadIdx.x / T_PER_ROW;
    const int row  = b * SS + blockIdx.x * ROWS_PB + lrow;
    const int t    = threadIdx.x % T_PER_ROW;

    float ax, ay;
    row_force(sp, row, t, ax, ay);

    if (t == 0) {
        float2 si = sp[blockIdx.x * ROWS_PB + lrow];
        float k2x = ax - si.x;
        float k2y = ay - si.y;
        float2 k1 = g_k1[row];
        float2 p  = p_old ? p_old[row] : g_p[row];
        float  r  = g_r[row];
        float nx  = fmaf(HALF_DT_F, k1.x + k2x, p.x);
        float ny  = fmaf(HALF_DT_F, k1.y + k2y, p.y);
        float nn  = sqrtf(nx * nx + ny * ny);
        float sc  = r / (nn + EPS_F);
        float2 res = make_float2(nx * sc, ny * sc);
        if (p_out) p_out[row] = res;
        else       g_p[row]   = res;
    }
}

// ============================================================================
// Launch: compress + index-build + 3 x (stepA, stepB). All graph-capturable.
// ============================================================================
extern "C" void kernel_launch(void* const* d_in, const int* in_sizes, int n_in,
                              void* d_out, int out_size) {
    const float* psi  = (const float*)d_in[0];
    const float* mask = (const float*)d_in[1];
    if (n_in >= 2 && in_sizes[0] > in_sizes[1]) {  // defensive: pick by size
        psi  = (const float*)d_in[1];
        mask = (const float*)d_in[0];
    }

    compress_kernel<<<1184, 256>>>(mask);
    build_idx_kernel<<<NROWS / 8, 256>>>();   // 8 warps/block, 1 warp/row

    dim3 gridF(SS / ROWS_PB, BB);             // (128, 4) = 512 blocks
    const int tpb = ROWS_PB * T_PER_ROW;      // 256 threads

    // step 1: read psi input directly
    stepA_kernel<<<gridF, tpb>>>((const float2*)psi);
    stepB_kernel<<<gridF, tpb>>>((const float2*)psi, nullptr);
    // step 2: state in g_p
    stepA_kernel<<<gridF, tpb>>>(nullptr);
    stepB_kernel<<<gridF, tpb>>>(nullptr, nullptr);
    // step 3: final result straight into d_out
    stepA_kernel<<<gridF, tpb>>>(nullptr);
    stepB_kernel<<<gridF, tpb>>>(nullptr, (float2*)d_out);

    (void)out_size;
}

// round 6
// speedup vs baseline: 1.2180x; 1.2180x over previous
#include <cuda_runtime.h>
#include <stdint.h>

// Problem constants (fixed by the reference: B=4, S=4096, D=2, 3 RK2 steps)
#define BB    4
#define SS    4096
#define WPR   (SS / 32)            // 128 bitmask words per row
#define NWRDS (BB * SS * WPR)      // 2,097,152 words (8 MB)
#define NROWS (BB * SS)            // 16384 rows
#define CAP   96                   // padded index capacity per row (mean 41, sd 6.4)
#define DT_F      0.1f
#define HALF_DT_F 0.05f
#define EPS_F     1e-8f

// Force-kernel tiling: 16 threads cooperate on one row (no smem, pure L2 gather).
#define T_PER_ROW 16
#define IPT       (CAP / T_PER_ROW)   // 6 indices per thread
#define WPT       (WPR / T_PER_ROW)   // 8 bitmask words per thread (fallback path)

// ---- scratch (static device globals; no runtime allocation) ----
__device__ __align__(16) uint32_t       g_bits[NWRDS];        // 8 MB bitmask
__device__ __align__(16) unsigned short g_idx[NROWS * CAP];   // 3 MB padded CSR indices
__device__               int            g_cnt[NROWS];         // true nnz per row
__device__ __align__(16) float2         g_p[NROWS];
__device__ __align__(16) float2         g_star[NROWS];
__device__ __align__(16) float2         g_k1[NROWS];
__device__               float          g_r[NROWS];

// ============================================================================
// 1) Compress dense fp32 0/1 mask -> bitmask via warp ballots (HBM-bound;
//    256 MB mandatory read, this is the floor of the whole problem).
// ============================================================================
__global__ void compress_kernel(const float* __restrict__ mask) {
    const int lane   = threadIdx.x & 31;
    const int warp   = (blockIdx.x * blockDim.x + threadIdx.x) >> 5;
    const int nwarps = (gridDim.x * blockDim.x) >> 5;

    for (size_t w = (size_t)warp * 8; w < (size_t)NWRDS; w += (size_t)nwarps * 8) {
        float v0 = mask[(w + 0) * 32 + lane];
        float v1 = mask[(w + 1) * 32 + lane];
        float v2 = mask[(w + 2) * 32 + lane];
        float v3 = mask[(w + 3) * 32 + lane];
        float v4 = mask[(w + 4) * 32 + lane];
        float v5 = mask[(w + 5) * 32 + lane];
        float v6 = mask[(w + 6) * 32 + lane];
        float v7 = mask[(w + 7) * 32 + lane];

        unsigned b0 = __ballot_sync(0xFFFFFFFFu, v0 != 0.0f);
        unsigned b1 = __ballot_sync(0xFFFFFFFFu, v1 != 0.0f);
        unsigned b2 = __ballot_sync(0xFFFFFFFFu, v2 != 0.0f);
        unsigned b3 = __ballot_sync(0xFFFFFFFFu, v3 != 0.0f);
        unsigned b4 = __ballot_sync(0xFFFFFFFFu, v4 != 0.0f);
        unsigned b5 = __ballot_sync(0xFFFFFFFFu, v5 != 0.0f);
        unsigned b6 = __ballot_sync(0xFFFFFFFFu, v6 != 0.0f);
        unsigned b7 = __ballot_sync(0xFFFFFFFFu, v7 != 0.0f);

        if (lane == 0) {
            uint4* dst = reinterpret_cast<uint4*>(g_bits + w);  // w % 8 == 0 -> 32B aligned
            dst[0] = make_uint4(b0, b1, b2, b3);
            dst[1] = make_uint4(b4, b5, b6, b7);
        }
    }
}

// ============================================================================
// 2) Build padded CSR index lists from the bitmask. One warp per row:
//    popc + warp prefix scan + in-bit-order scatter -> fully deterministic.
// ============================================================================
__global__ void build_idx_kernel() {
    const int warp_in_blk = threadIdx.x >> 5;
    const int lane        = threadIdx.x & 31;
    const int row         = blockIdx.x * (blockDim.x >> 5) + warp_in_blk;
    if (row >= NROWS) return;

    const uint4 w4 = reinterpret_cast<const uint4*>(g_bits + (size_t)row * WPR)[lane];
    const int n = __popc(w4.x) + __popc(w4.y) + __popc(w4.z) + __popc(w4.w);

    int pfx = n;
#pragma unroll
    for (int off = 1; off < 32; off <<= 1) {
        int v = __shfl_up_sync(0xFFFFFFFFu, pfx, off);
        if (lane >= off) pfx += v;
    }
    const int total = __shfl_sync(0xFFFFFFFFu, pfx, 31);
    pfx -= n;  // exclusive

    if (lane == 31) g_cnt[row] = total;

    unsigned short* dst = g_idx + (size_t)row * CAP;
    int slot = pfx;
    const int colbase = lane * 128;  // lane*4 words * 32 bits
    uint32_t ws[4] = {w4.x, w4.y, w4.z, w4.w};
#pragma unroll
    for (int k = 0; k < 4; k++) {
        uint32_t w = ws[k];
        while (w) {
            int c = __ffs(w) - 1;
            w &= (w - 1);
            if (slot < CAP) dst[slot] = (unsigned short)(colbase + k * 32 + c);
            slot++;
        }
    }
}

// ============================================================================
// Force helper: sum over the row's nonzero columns, gathering DIRECTLY from
// global (the 128 KB state is L2-resident). No smem, no syncthreads.
// ============================================================================
__device__ __forceinline__ void row_force(const float2* __restrict__ base,
                                          int row, int t,
                                          float& ax, float& ay) {
    ax = 0.0f; ay = 0.0f;
    const int cnt = g_cnt[row];

    if (cnt <= CAP) {
        // 6 independent predicated LDG.64 gathers per thread.
        const unsigned int* p = reinterpret_cast<const unsigned int*>(
            g_idx + (size_t)row * CAP + t * IPT);   // t*6 u16 = 12B -> 4B aligned
        unsigned int a0 = p[0], a1 = p[1], a2 = p[2];
        int id[IPT];
        id[0] = (int)(a0 & 0xFFFFu);  id[1] = (int)(a0 >> 16);
        id[2] = (int)(a1 & 0xFFFFu);  id[3] = (int)(a1 >> 16);
        id[4] = (int)(a2 & 0xFFFFu);  id[5] = (int)(a2 >> 16);

        const int off = t * IPT;
#pragma unroll
        for (int j = 0; j < IPT; j++) {
            if (off + j < cnt) {
                float2 v = base[id[j]];
                ax += v.x;
                ay += v.y;
            }
        }
    } else {
        // Correctness fallback (cnt > CAP, ~never): scan this thread's bitmask words.
        const uint32_t* wr = g_bits + (size_t)row * WPR + t * WPT;
#pragma unroll
        for (int q = 0; q < WPT; q++) {
            uint32_t w = wr[q];
            int wbase = (t * WPT + q) * 32;
            while (w) {
                int c = __ffs(w) - 1;
                w &= (w - 1);
                float2 v = base[wbase + c];
                ax += v.x;
                ay += v.y;
            }
        }
    }

#pragma unroll
    for (int offp = T_PER_ROW / 2; offp > 0; offp >>= 1) {
        ax += __shfl_down_sync(0xFFFFFFFFu, ax, offp, T_PER_ROW);
        ay += __shfl_down_sync(0xFFFFFFFFu, ay, offp, T_PER_ROW);
    }
}

// ============================================================================
// 3a) stepA: from p -> (r, k1, psi_star).   p_in==nullptr means "use g_p".
// ============================================================================
__global__ void __launch_bounds__(256)
stepA_kernel(const float2* __restrict__ p_in) {
    const int gid = blockIdx.x * blockDim.x + threadIdx.x;
    const int row = gid / T_PER_ROW;
    const int t   = gid % T_PER_ROW;

    const float2* __restrict__ src  = p_in ? p_in : g_p;
    const float2* __restrict__ base = src + (row >> 12) * SS;  // batch base

    float ax, ay;
    row_force(base, row, t, ax, ay);

    if (t == 0) {
        float2 pi = src[row];
        float  r  = sqrtf(pi.x * pi.x + pi.y * pi.y);
        float k1x = ax - pi.x;
        float k1y = ay - pi.y;
        float sx  = fmaf(DT_F, k1x, pi.x);
        float sy  = fmaf(DT_F, k1y, pi.y);
        float sn  = sqrtf(sx * sx + sy * sy);
        float sc  = r / (sn + EPS_F);
        g_star[row] = make_float2(sx * sc, sy * sc);
        g_k1[row]   = make_float2(k1x, k1y);
        g_r[row]    = r;
    }
}

// ============================================================================
// 3b) stepB: from (psi_star, k1, p, r) -> p_new.
//     p_old==nullptr -> use g_p.  p_out==nullptr -> write g_p.
// ============================================================================
__global__ void __launch_bounds__(256)
stepB_kernel(const float2* __restrict__ p_old, float2* __restrict__ p_out) {
    const int gid = blockIdx.x * blockDim.x + threadIdx.x;
    const int row = gid / T_PER_ROW;
    const int t   = gid % T_PER_ROW;

    const float2* __restrict__ base = g_star + (row >> 12) * SS;  // batch base

    float ax, ay;
    row_force(base, row, t, ax, ay);

    if (t == 0) {
        float2 si = g_star[row];
        float k2x = ax - si.x;
        float k2y = ay - si.y;
        float2 k1 = g_k1[row];
        float2 p  = p_old ? p_old[row] : g_p[row];
        float  r  = g_r[row];
        float nx  = fmaf(HALF_DT_F, k1.x + k2x, p.x);
        float ny  = fmaf(HALF_DT_F, k1.y + k2y, p.y);
        float nn  = sqrtf(nx * nx + ny * ny);
        float sc  = r / (nn + EPS_F);
        float2 res = make_float2(nx * sc, ny * sc);
        if (p_out) p_out[row] = res;
        else       g_p[row]   = res;
    }
}

// ============================================================================
// Launch: compress + index-build + 3 x (stepA, stepB). All graph-capturable.
// ============================================================================
extern "C" void kernel_launch(void* const* d_in, const int* in_sizes, int n_in,
                              void* d_out, int out_size) {
    const float* psi  = (const float*)d_in[0];
    const float* mask = (const float*)d_in[1];
    if (n_in >= 2 && in_sizes[0] > in_sizes[1]) {  // defensive: pick by size
        psi  = (const float*)d_in[1];
        mask = (const float*)d_in[0];
    }

    compress_kernel<<<1184, 256>>>(mask);
    build_idx_kernel<<<NROWS / 8, 256>>>();   // 8 warps/block, 1 warp/row

    const int nthreads = NROWS * T_PER_ROW;   // 262144
    const int gridF    = nthreads / 256;      // 1024 blocks

    // step 1: read psi input directly
    stepA_kernel<<<gridF, 256>>>((const float2*)psi);
    stepB_kernel<<<gridF, 256>>>((const float2*)psi, nullptr);
    // step 2: state in g_p
    stepA_kernel<<<gridF, 256>>>(nullptr);
    stepB_kernel<<<gridF, 256>>>(nullptr, nullptr);
    // step 3: final result straight into d_out
    stepA_kernel<<<gridF, 256>>>(nullptr);
    stepB_kernel<<<gridF, 256>>>(nullptr, (float2*)d_out);

    (void)out_size;
}